// round 1
// baseline (speedup 1.0000x reference)
#include <cuda_runtime.h>
#include <math.h>
#include <stdint.h>

// ---- problem constants ----
#define BB  16
#define HH  384
#define WW  512
#define HPP 191   // pooled H: (384-2)/2
#define WPP 255   // pooled W: (512-2)/2
#define H2D 189
#define W2D 253
#define H3D 187
#define W3D 251
#define NPIX (H3D*W3D)   // 46937
#define NEGV (-1e30f)
#define THRESH_V 0.6f
#define KPICKS 128
#define CAP 5600

// ---- scratch (static device globals; no allocation allowed) ----
__device__ float g_pool[BB*10*HPP*WPP];     // conv1+prelu+pool output
__device__ float g_h2[BB*16*H2D*W2D];       // conv2+prelu output
__device__ float g_scores[BB*NPIX];         // masked scores (>=0.6 or NEG)
__device__ float g_reg[BB*NPIX*4];          // reg head per pixel
__device__ int   g_cand[BB*NPIX];           // compacted candidate pixel ids
__device__ float g_cand_sc[BB*NPIX];        // compacted candidate scores

// ============================================================
// K1: normalize + conv1(3x3,3->10) + bias + PReLU + maxpool2x2
// one thread per pooled output pixel, all 10 channels
// ============================================================
__global__ void k1_conv1_pool(const float* __restrict__ im,
                              const float* __restrict__ w,   // (10,3,3,3)
                              const float* __restrict__ b,   // (10)
                              const float* __restrict__ p)   // (10)
{
    __shared__ float sw[270];
    __shared__ float sb[10];
    __shared__ float sp[10];
    int tid = threadIdx.y * blockDim.x + threadIdx.x;
    for (int i = tid; i < 270; i += 256) sw[i] = w[i];
    if (tid < 10) { sb[tid] = b[tid]; sp[tid] = p[tid]; }
    __syncthreads();

    int ox = blockIdx.x * 32 + threadIdx.x;
    int oy = blockIdx.y * 8  + threadIdx.y;
    int bb = blockIdx.z;
    if (ox >= WPP || oy >= HPP) return;

    // input window: rows 2oy..2oy+3, cols 2ox..2ox+3, 3 channels
    float win[3][4][4];
    int iy0 = 2*oy, ix0 = 2*ox;
#pragma unroll
    for (int c = 0; c < 3; c++) {
        const float* base = im + ((bb*3 + c)*HH + iy0)*WW + ix0;
#pragma unroll
        for (int iy = 0; iy < 4; iy++) {
#pragma unroll
            for (int ix = 0; ix < 4; ix++) {
                win[c][iy][ix] = (base[iy*WW + ix] - 127.5f) * 0.0078125f;
            }
        }
    }

#pragma unroll
    for (int oc = 0; oc < 10; oc++) {
        float a00 = sb[oc], a01 = sb[oc], a10 = sb[oc], a11 = sb[oc];
#pragma unroll
        for (int c = 0; c < 3; c++) {
#pragma unroll
            for (int ky = 0; ky < 3; ky++) {
#pragma unroll
                for (int kx = 0; kx < 3; kx++) {
                    float wv = sw[((oc*3 + c)*3 + ky)*3 + kx];
                    a00 = fmaf(wv, win[c][ky  ][kx  ], a00);
                    a01 = fmaf(wv, win[c][ky  ][kx+1], a01);
                    a10 = fmaf(wv, win[c][ky+1][kx  ], a10);
                    a11 = fmaf(wv, win[c][ky+1][kx+1], a11);
                }
            }
        }
        float al = sp[oc];
        a00 = a00 > 0.f ? a00 : al*a00;
        a01 = a01 > 0.f ? a01 : al*a01;
        a10 = a10 > 0.f ? a10 : al*a10;
        a11 = a11 > 0.f ? a11 : al*a11;
        float m = fmaxf(fmaxf(a00, a01), fmaxf(a10, a11));
        g_pool[((bb*10 + oc)*HPP + oy)*WPP + ox] = m;
    }
}

// ============================================================
// K2: conv2(3x3,10->16) + bias + PReLU
// ============================================================
__global__ void k2_conv2(const float* __restrict__ w,   // (16,10,3,3)
                         const float* __restrict__ b,   // (16)
                         const float* __restrict__ p)   // (16)
{
    __shared__ float sw[1440];
    __shared__ float sb[16];
    __shared__ float sp[16];
    int tid = threadIdx.y * blockDim.x + threadIdx.x;
    for (int i = tid; i < 1440; i += 256) sw[i] = w[i];
    if (tid < 16) { sb[tid] = b[tid]; sp[tid] = p[tid]; }
    __syncthreads();

    int ox = blockIdx.x * 32 + threadIdx.x;
    int oy = blockIdx.y * 8  + threadIdx.y;
    int bb = blockIdx.z;
    if (ox >= W2D || oy >= H2D) return;

    float acc[16];
#pragma unroll
    for (int oc = 0; oc < 16; oc++) acc[oc] = sb[oc];

#pragma unroll
    for (int c = 0; c < 10; c++) {
        float u[9];
        const float* base = g_pool + ((bb*10 + c)*HPP + oy)*WPP + ox;
#pragma unroll
        for (int ky = 0; ky < 3; ky++) {
#pragma unroll
            for (int kx = 0; kx < 3; kx++) u[ky*3+kx] = base[ky*WPP + kx];
        }
#pragma unroll
        for (int oc = 0; oc < 16; oc++) {
            const float* wp = &sw[(oc*10 + c)*9];
#pragma unroll
            for (int k = 0; k < 9; k++) acc[oc] = fmaf(wp[k], u[k], acc[oc]);
        }
    }
#pragma unroll
    for (int oc = 0; oc < 16; oc++) {
        float v = acc[oc];
        v = v > 0.f ? v : sp[oc]*v;
        g_h2[((bb*16 + oc)*H2D + oy)*W2D + ox] = v;
    }
}

// ============================================================
// K3: conv3(3x3,16->32)+PReLU  fused with 1x1 heads:
//     softmax-prob (2ch) -> masked score, reg (4ch)
// ============================================================
__global__ void k3_conv3_heads(const float* __restrict__ w3,  // (32,16,3,3)
                               const float* __restrict__ b3,  // (32)
                               const float* __restrict__ p3,  // (32)
                               const float* __restrict__ w41, // (2,32)
                               const float* __restrict__ b41, // (2)
                               const float* __restrict__ w42, // (4,32)
                               const float* __restrict__ b42) // (4)
{
    __shared__ float sw[4608];
    __shared__ float sb[32], sp[32];
    __shared__ float sw41[64], sb41[2], sw42[128], sb42[4];
    int tid = threadIdx.y * blockDim.x + threadIdx.x;
    for (int i = tid; i < 4608; i += 256) sw[i] = w3[i];
    if (tid < 32) { sb[tid] = b3[tid]; sp[tid] = p3[tid]; }
    if (tid < 64)  sw41[tid] = w41[tid];
    if (tid < 2)   sb41[tid] = b41[tid];
    if (tid < 128) sw42[tid] = w42[tid];
    if (tid < 4)   sb42[tid] = b42[tid];
    __syncthreads();

    int ox = blockIdx.x * 32 + threadIdx.x;
    int oy = blockIdx.y * 8  + threadIdx.y;
    int bb = blockIdx.z;
    if (ox >= W3D || oy >= H3D) return;

    float acc[32];
#pragma unroll
    for (int oc = 0; oc < 32; oc++) acc[oc] = sb[oc];

    for (int c = 0; c < 16; c++) {
        float u[9];
        const float* base = g_h2 + ((bb*16 + c)*H2D + oy)*W2D + ox;
#pragma unroll
        for (int ky = 0; ky < 3; ky++) {
#pragma unroll
            for (int kx = 0; kx < 3; kx++) u[ky*3+kx] = base[ky*W2D + kx];
        }
#pragma unroll
        for (int oc = 0; oc < 32; oc++) {
            const float* wp = &sw[(oc*16 + c)*9];
#pragma unroll
            for (int k = 0; k < 9; k++) acc[oc] = fmaf(wp[k], u[k], acc[oc]);
        }
    }
#pragma unroll
    for (int oc = 0; oc < 32; oc++) {
        float v = acc[oc];
        acc[oc] = v > 0.f ? v : sp[oc]*v;
    }

    // heads
    float l0 = sb41[0], l1 = sb41[1];
    float r0 = sb42[0], r1 = sb42[1], r2 = sb42[2], r3 = sb42[3];
#pragma unroll
    for (int i = 0; i < 32; i++) {
        float h = acc[i];
        l0 = fmaf(h, sw41[i],      l0);
        l1 = fmaf(h, sw41[32 + i], l1);
        r0 = fmaf(h, sw42[i],      r0);
        r1 = fmaf(h, sw42[32 + i], r1);
        r2 = fmaf(h, sw42[64 + i], r2);
        r3 = fmaf(h, sw42[96 + i], r3);
    }
    float prob = 1.f / (1.f + expf(l0 - l1));
    int pix = oy * W3D + ox;
    g_scores[bb*NPIX + pix] = (prob >= THRESH_V) ? prob : NEGV;
    float* rg = &g_reg[(bb*NPIX + pix)*4];
    rg[0] = r0; rg[1] = r1; rg[2] = r2; rg[3] = r3;
}

// ============================================================
// K4: per-batch compaction + iterative argmax NMS + refine
// IoU>0.5 between two 12x12 stride-2 boxes  <=>  |dgx|<=1 && |dgy|<=1
// ============================================================
__global__ void k4_nms(float* __restrict__ out)
{
    int bb = blockIdx.x;
    int tid = threadIdx.x;
    const int NT = 256;

    __shared__ int   s_pix[CAP];
    __shared__ float s_sc[CAP];
    __shared__ float red_s[NT];
    __shared__ int   red_i[NT];
    __shared__ int   wcnt[8];
    __shared__ int   s_count;
    __shared__ int   s_j;
    __shared__ float s_best;

    if (tid == 0) s_count = 0;
    __syncthreads();

    // ---- ordered compaction of candidates (score >= THRESH) ----
    const float* sc_g = g_scores + bb*NPIX;
    int  lane = tid & 31;
    int  wrp  = tid >> 5;
    for (int start = 0; start < NPIX; start += NT) {
        int i = start + tid;
        float v = (i < NPIX) ? sc_g[i] : NEGV;
        bool f = (v >= THRESH_V);
        unsigned m = __ballot_sync(0xffffffffu, f);
        if (lane == 0) wcnt[wrp] = __popc(m);
        __syncthreads();
        if (tid == 0) {
            int s = s_count;
#pragma unroll
            for (int k = 0; k < 8; k++) { int t = wcnt[k]; wcnt[k] = s; s += t; }
            s_count = s;
        }
        __syncthreads();
        if (f) {
            int pos = wcnt[wrp] + __popc(m & ((1u << lane) - 1u));
            if (pos < CAP) { s_pix[pos] = i; s_sc[pos] = v; }
            g_cand[bb*NPIX + pos]    = i;
            g_cand_sc[bb*NPIX + pos] = v;
        }
        __syncthreads();
    }
    int count = s_count;
    bool use_sh = (count <= CAP);
    int*   pixp = use_sh ? s_pix : (g_cand    + bb*NPIX);
    float* scp  = use_sh ? s_sc  : (g_cand_sc + bb*NPIX);

    // ---- NMS picks ----
    for (int k = 0; k < KPICKS; k++) {
        // argmax with first-occurrence tie-break (lowest index)
        float bs = -INFINITY; int bi = -1;
        for (int i = tid; i < count; i += NT) {
            float v = scp[i];
            if (v > bs) { bs = v; bi = i; }
        }
        red_s[tid] = bs; red_i[tid] = bi;
        __syncthreads();
        for (int off = NT/2; off > 0; off >>= 1) {
            if (tid < off) {
                float v = red_s[tid + off]; int ii = red_i[tid + off];
                float c = red_s[tid];       int ci = red_i[tid];
                if (v > c || (v == c && ii != -1 && (ci == -1 || ii < ci))) {
                    red_s[tid] = v; red_i[tid] = ii;
                }
            }
            __syncthreads();
        }
        if (tid == 0) { s_best = red_s[0]; s_j = red_i[0]; }
        __syncthreads();
        float best = s_best;
        int j = s_j;

        if (!(best > -0.5e30f)) {
            // exhausted: every remaining pick has ok=false -> zero rows
            int n0 = (KPICKS - k) * 5;
            float* o0 = out + ((size_t)bb*KPICKS + k)*5;
            for (int t = tid; t < n0; t += NT) o0[t] = 0.f;
            break;
        }

        int jp = pixp[j];
        int jx = jp % W3D, jy = jp / W3D;
        // suppress 3x3 grid neighborhood (includes j itself)
        for (int i = tid; i < count; i += NT) {
            int p = pixp[i];
            int cx = p % W3D, cy = p / W3D;
            int dx = cx - jx; if (dx < 0) dx = -dx;
            int dy = cy - jy; if (dy < 0) dy = -dy;
            if (dx <= 1 && dy <= 1) scp[i] = NEGV;
        }
        if (tid == 0) {
            float x1 = 2.f*jx + 1.f,  y1 = 2.f*jy + 1.f;
            float x2 = 2.f*jx + 12.f, y2 = 2.f*jy + 12.f;
            const float* r = &g_reg[((size_t)bb*NPIX + jp)*4];
            float q1 = fmaf(r[0], 11.f, x1);
            float q2 = fmaf(r[1], 11.f, y1);
            float q3 = fmaf(r[2], 11.f, x2);
            float q4 = fmaf(r[3], 11.f, y2);
            float rw = q3 - q1, rh = q4 - q2;
            float l = fmaxf(rw, rh);
            float nx1 = q1 + rw*0.5f - l*0.5f;
            float ny1 = q2 + rh*0.5f - l*0.5f;
            float* o = out + ((size_t)bb*KPICKS + k)*5;
            o[0] = nx1; o[1] = ny1; o[2] = nx1 + l; o[3] = ny1 + l; o[4] = best;
        }
        __syncthreads();
    }
}

// ============================================================
extern "C" void kernel_launch(void* const* d_in, const int* in_sizes, int n_in,
                              void* d_out, int out_size)
{
    const float* im   = (const float*)d_in[0];
    const float* c1w  = (const float*)d_in[1];
    const float* c1b  = (const float*)d_in[2];
    const float* p1   = (const float*)d_in[3];
    const float* c2w  = (const float*)d_in[4];
    const float* c2b  = (const float*)d_in[5];
    const float* p2   = (const float*)d_in[6];
    const float* c3w  = (const float*)d_in[7];
    const float* c3b  = (const float*)d_in[8];
    const float* p3   = (const float*)d_in[9];
    const float* c41w = (const float*)d_in[10];
    const float* c41b = (const float*)d_in[11];
    const float* c42w = (const float*)d_in[12];
    const float* c42b = (const float*)d_in[13];
    float* out = (float*)d_out;

    dim3 blk(32, 8, 1);
    dim3 g1((WPP + 31)/32, (HPP + 7)/8, BB);
    dim3 g2((W2D + 31)/32, (H2D + 7)/8, BB);
    dim3 g3((W3D + 31)/32, (H3D + 7)/8, BB);

    k1_conv1_pool<<<g1, blk>>>(im, c1w, c1b, p1);
    k2_conv2<<<g2, blk>>>(c2w, c2b, p2);
    k3_conv3_heads<<<g3, blk>>>(c3w, c3b, p3, c41w, c41b, c42w, c42b);
    k4_nms<<<BB, 256>>>(out);
}

// round 2
// speedup vs baseline: 1.4133x; 1.4133x over previous
#include <cuda_runtime.h>
#include <math.h>

// ---- problem constants ----
#define BB  16
#define HH  384
#define WW  512
#define HPP 191   // pooled H: (384-2)/2
#define WPP 255   // pooled W: (512-2)/2
#define H2D 189
#define W2D 253
#define H3D 187
#define W3D 251
#define NPIX (H3D*W3D)   // 46937
#define NEGV (-1e30f)
#define THRESH_V 0.6f
#define KPICKS 128
#define CAP 5600
#define PAIRS3 126       // ceil(251/2)
#define PAIRS2 127       // ceil(253/2)

// ---- scratch (static device globals; no allocation allowed) ----
// +16 padding: packed-pair kernels read one column past the right edge for the
// discarded second lane of the last pair; keep those reads in-bounds.
__device__ float  g_pool[BB*10*HPP*WPP + 16];
__device__ float  g_h2[BB*16*H2D*W2D + 16];
__device__ int    g_cnt[BB];
__device__ int    g_cand[BB*NPIX];      // packed (y<<16)|x per candidate
__device__ float  g_cand_sc[BB*NPIX];
__device__ float4 g_cand_reg[BB*NPIX];

// ---- f32x2 packed helpers (sm_103a: ptxas never auto-fuses these) ----
__device__ __forceinline__ unsigned long long pack2(float lo, float hi){
    unsigned long long r;
    asm("mov.b64 %0, {%1, %2};" : "=l"(r) : "f"(lo), "f"(hi));
    return r;
}
__device__ __forceinline__ void unpack2(unsigned long long v, float &lo, float &hi){
    asm("mov.b64 {%0, %1}, %2;" : "=f"(lo), "=f"(hi) : "l"(v));
}
__device__ __forceinline__ void fma2(unsigned long long &d, unsigned long long a, unsigned long long b){
    asm("fma.rn.f32x2 %0, %1, %2, %0;" : "+l"(d) : "l"(a), "l"(b));
}

// ============================================================
// K0: zero per-batch candidate counters
// ============================================================
__global__ void k0_zero(){
    if (threadIdx.x < BB) g_cnt[threadIdx.x] = 0;
}

// ============================================================
// K1: normalize + conv1(3x3,3->10) + PReLU + maxpool2x2
// one thread per pooled pixel; 4 conv pixels as 2 packed x-pairs
// ============================================================
__global__ __launch_bounds__(256) void k1_conv1_pool(const float* __restrict__ im,
                              const float* __restrict__ w,   // (10,3,3,3)
                              const float* __restrict__ b,
                              const float* __restrict__ p)
{
    __shared__ __align__(16) unsigned long long sw[270];  // dup pairs, layout [(c*9+k)*10 + oc]
    __shared__ float sb[10], sp[10];
    int tid = threadIdx.y * 32 + threadIdx.x;
    for (int i = tid; i < 270; i += 256){
        int oc = i / 27, rem = i % 27;      // i = oc*27 + c*9 + k
        float v = w[i];
        sw[rem*10 + oc] = pack2(v, v);
    }
    if (tid < 10){ sb[tid] = b[tid]; sp[tid] = p[tid]; }
    __syncthreads();

    int ox = blockIdx.x * 32 + threadIdx.x;
    int oy = blockIdx.y * 8  + threadIdx.y;
    int bb = blockIdx.z;
    if (ox >= WPP || oy >= HPP) return;

    unsigned long long at[10], ab[10];     // (a00,a01) and (a10,a11)
#pragma unroll
    for (int oc = 0; oc < 10; oc++){ at[oc] = pack2(sb[oc], sb[oc]); ab[oc] = at[oc]; }

    int iy0 = 2*oy, ix0 = 2*ox;
#pragma unroll
    for (int c = 0; c < 3; c++){
        const float* base = im + ((bb*3 + c)*HH + iy0)*WW + ix0;
        float rw[4][4];
#pragma unroll
        for (int r = 0; r < 4; r++)
#pragma unroll
            for (int x = 0; x < 4; x++)
                rw[r][x] = (base[r*WW + x] - 127.5f) * 0.0078125f;
        unsigned long long rp[4][3];
#pragma unroll
        for (int r = 0; r < 4; r++)
#pragma unroll
            for (int x = 0; x < 3; x++)
                rp[r][x] = pack2(rw[r][x], rw[r][x+1]);
#pragma unroll
        for (int ky = 0; ky < 3; ky++)
#pragma unroll
        for (int kx = 0; kx < 3; kx++){
            int k = ky*3 + kx;
            const ulonglong2* wp = reinterpret_cast<const ulonglong2*>(&sw[(c*9 + k)*10]);
            unsigned long long ut = rp[ky][kx], ub = rp[ky+1][kx];
#pragma unroll
            for (int g = 0; g < 5; g++){
                ulonglong2 wv = wp[g];
                fma2(at[2*g],   ut, wv.x);  fma2(ab[2*g],   ub, wv.x);
                fma2(at[2*g+1], ut, wv.y);  fma2(ab[2*g+1], ub, wv.y);
            }
        }
    }
#pragma unroll
    for (int oc = 0; oc < 10; oc++){
        float a00,a01,a10,a11;
        unpack2(at[oc], a00, a01);
        unpack2(ab[oc], a10, a11);
        float al = sp[oc];
        a00 = a00 > 0.f ? a00 : al*a00;
        a01 = a01 > 0.f ? a01 : al*a01;
        a10 = a10 > 0.f ? a10 : al*a10;
        a11 = a11 > 0.f ? a11 : al*a11;
        g_pool[((bb*10 + oc)*HPP + oy)*WPP + ox] = fmaxf(fmaxf(a00,a01), fmaxf(a10,a11));
    }
}

// ============================================================
// K2: conv2(3x3,10->16) + PReLU, 2 pixels/thread packed f32x2
// ============================================================
__global__ __launch_bounds__(256) void k2_conv2(const float* __restrict__ w,  // (16,10,3,3)
                         const float* __restrict__ b,
                         const float* __restrict__ p)
{
    __shared__ __align__(16) unsigned long long sw[1440]; // [(c*9+k)*16 + oc] dup pairs
    __shared__ float sb[16], sp[16];
    int tid = threadIdx.y * 32 + threadIdx.x;
    for (int i = tid; i < 1440; i += 256){
        int oc = i / 90, rem = i % 90;
        float v = w[i];
        sw[rem*16 + oc] = pack2(v, v);
    }
    if (tid < 16){ sb[tid] = b[tid]; sp[tid] = p[tid]; }
    __syncthreads();

    int pp = blockIdx.x * 32 + threadIdx.x;
    int oy = blockIdx.y * 8  + threadIdx.y;
    int bb = blockIdx.z;
    if (pp >= PAIRS2 || oy >= H2D) return;
    int x0 = 2*pp;

    unsigned long long acc[16];
#pragma unroll
    for (int oc = 0; oc < 16; oc++) acc[oc] = pack2(sb[oc], sb[oc]);

    for (int c = 0; c < 10; c++){
        const float* base = g_pool + ((bb*10 + c)*HPP + oy)*WPP + x0;
        unsigned long long u[9];
#pragma unroll
        for (int ky = 0; ky < 3; ky++){
            float v0 = base[ky*WPP+0], v1 = base[ky*WPP+1];
            float v2 = base[ky*WPP+2], v3 = base[ky*WPP+3];
            u[ky*3+0] = pack2(v0,v1); u[ky*3+1] = pack2(v1,v2); u[ky*3+2] = pack2(v2,v3);
        }
#pragma unroll
        for (int k = 0; k < 9; k++){
            const ulonglong2* wp = reinterpret_cast<const ulonglong2*>(&sw[(c*9 + k)*16]);
            unsigned long long uu = u[k];
#pragma unroll
            for (int g = 0; g < 8; g++){
                ulonglong2 wv = wp[g];
                fma2(acc[2*g],   uu, wv.x);
                fma2(acc[2*g+1], uu, wv.y);
            }
        }
    }
    bool x1ok = (x0 + 1) < W2D;
#pragma unroll
    for (int oc = 0; oc < 16; oc++){
        float va, vb; unpack2(acc[oc], va, vb);
        float al = sp[oc];
        va = va > 0.f ? va : al*va;
        vb = vb > 0.f ? vb : al*vb;
        float* o = &g_h2[((bb*16 + oc)*H2D + oy)*W2D + x0];
        o[0] = va;
        if (x1ok) o[1] = vb;
    }
}

// ============================================================
// K3: conv3(3x3,16->32)+PReLU + fused 1x1 heads + candidate append
// 2 pixels/thread packed f32x2
// ============================================================
__global__ __launch_bounds__(256) void k3_conv3_heads(const float* __restrict__ w3, // (32,16,3,3)
                               const float* __restrict__ b3,
                               const float* __restrict__ p3,
                               const float* __restrict__ w41, const float* __restrict__ b41,
                               const float* __restrict__ w42, const float* __restrict__ b42)
{
    __shared__ __align__(16) unsigned long long sw[4608]; // [(c*9+k)*32 + oc] dup pairs
    __shared__ float sb[32], sp[32];
    __shared__ float sw41[64], sw42[128], sb41[2], sb42[4];
    int tid = threadIdx.y * 32 + threadIdx.x;
    for (int i = tid; i < 4608; i += 256){
        int oc = i / 144, rem = i % 144;
        float v = w3[i];
        sw[rem*32 + oc] = pack2(v, v);
    }
    if (tid < 32){ sb[tid] = b3[tid]; sp[tid] = p3[tid]; }
    if (tid < 64)  sw41[tid] = w41[tid];
    if (tid < 128) sw42[tid] = w42[tid];
    if (tid < 2)   sb41[tid] = b41[tid];
    if (tid < 4)   sb42[tid] = b42[tid];
    __syncthreads();

    int pp = blockIdx.x * 32 + threadIdx.x;
    int oy = blockIdx.y * 8  + threadIdx.y;
    int bb = blockIdx.z;
    if (pp >= PAIRS3 || oy >= H3D) return;
    int x0 = 2*pp;

    unsigned long long acc[32];
#pragma unroll
    for (int oc = 0; oc < 32; oc++) acc[oc] = pack2(sb[oc], sb[oc]);

    for (int c = 0; c < 16; c++){
        const float* base = g_h2 + ((bb*16 + c)*H2D + oy)*W2D + x0;
        unsigned long long u[9];
#pragma unroll
        for (int ky = 0; ky < 3; ky++){
            float v0 = base[ky*W2D+0], v1 = base[ky*W2D+1];
            float v2 = base[ky*W2D+2], v3 = base[ky*W2D+3];
            u[ky*3+0] = pack2(v0,v1); u[ky*3+1] = pack2(v1,v2); u[ky*3+2] = pack2(v2,v3);
        }
#pragma unroll
        for (int k = 0; k < 9; k++){
            const ulonglong2* wp = reinterpret_cast<const ulonglong2*>(&sw[(c*9 + k)*32]);
            unsigned long long uu = u[k];
#pragma unroll
            for (int g = 0; g < 16; g++){
                ulonglong2 wv = wp[g];
                fma2(acc[2*g],   uu, wv.x);
                fma2(acc[2*g+1], uu, wv.y);
            }
        }
    }

    // heads (scalar; ~400 instr vs ~7000 in the mainloop)
    float l0a = sb41[0], l1a = sb41[1], l0b = sb41[0], l1b = sb41[1];
    float r0a = sb42[0], r1a = sb42[1], r2a = sb42[2], r3a = sb42[3];
    float r0b = sb42[0], r1b = sb42[1], r2b = sb42[2], r3b = sb42[3];
#pragma unroll
    for (int oc = 0; oc < 32; oc++){
        float va, vb; unpack2(acc[oc], va, vb);
        float al = sp[oc];
        va = va > 0.f ? va : al*va;
        vb = vb > 0.f ? vb : al*vb;
        float wA = sw41[oc], wB = sw41[32+oc];
        l0a = fmaf(va, wA, l0a);  l0b = fmaf(vb, wA, l0b);
        l1a = fmaf(va, wB, l1a);  l1b = fmaf(vb, wB, l1b);
        float q0 = sw42[oc], q1 = sw42[32+oc], q2 = sw42[64+oc], q3 = sw42[96+oc];
        r0a = fmaf(va, q0, r0a);  r0b = fmaf(vb, q0, r0b);
        r1a = fmaf(va, q1, r1a);  r1b = fmaf(vb, q1, r1b);
        r2a = fmaf(va, q2, r2a);  r2b = fmaf(vb, q2, r2b);
        r3a = fmaf(va, q3, r3a);  r3b = fmaf(vb, q3, r3b);
    }
    float proba = 1.f / (1.f + expf(l0a - l1a));
    if (proba >= THRESH_V){
        int pos = atomicAdd(&g_cnt[bb], 1);
        if (pos < NPIX){
            g_cand[bb*NPIX + pos]    = (oy << 16) | x0;
            g_cand_sc[bb*NPIX + pos] = proba;
            g_cand_reg[bb*NPIX + pos] = make_float4(r0a, r1a, r2a, r3a);
        }
    }
    if (x0 + 1 < W3D){
        float probb = 1.f / (1.f + expf(l0b - l1b));
        if (probb >= THRESH_V){
            int pos = atomicAdd(&g_cnt[bb], 1);
            if (pos < NPIX){
                g_cand[bb*NPIX + pos]    = (oy << 16) | (x0 + 1);
                g_cand_sc[bb*NPIX + pos] = probb;
                g_cand_reg[bb*NPIX + pos] = make_float4(r0b, r1b, r2b, r3b);
            }
        }
    }
}

// ============================================================
// K4: per-batch iterative argmax NMS on the (unordered) candidate
// list. Tie-break: (score desc, packed (y,x) asc) == pixel-index
// order, so list order doesn't matter -> deterministic.
// IoU>0.5 for 12x12 stride-2 boxes  <=>  |dx|<=1 && |dy|<=1.
// ============================================================
__global__ void k4_nms(float* __restrict__ out)
{
    const int NT = 256;
    int bb = blockIdx.x, tid = threadIdx.x;
    int lane = tid & 31, wrp = tid >> 5;

    __shared__ float s_sc[CAP];
    __shared__ int   s_xy[CAP];
    __shared__ float w_s[8];
    __shared__ int   w_xy[8], w_i[8];
    __shared__ float sh_best;
    __shared__ int   sh_j, sh_xy;

    int count = g_cnt[bb];
    if (count > NPIX) count = NPIX;
    bool insh = (count <= CAP);
    float* scp;
    const int* xyp;
    if (insh){
        for (int i = tid; i < count; i += NT){
            s_sc[i] = g_cand_sc[bb*NPIX + i];
            s_xy[i] = g_cand[bb*NPIX + i];
        }
        scp = s_sc; xyp = s_xy;
    } else {
        scp = g_cand_sc + bb*NPIX;
        xyp = g_cand + bb*NPIX;
    }
    __syncthreads();

    for (int k = 0; k < KPICKS; k++){
        // argmax with (score desc, xy asc) tie-break
        float bs = -INFINITY; int bxy = 0x7fffffff; int bi = -1;
        for (int i = tid; i < count; i += NT){
            float v = scp[i]; int xy = xyp[i];
            if (v > bs || (v == bs && xy < bxy)){ bs = v; bxy = xy; bi = i; }
        }
#pragma unroll
        for (int off = 16; off > 0; off >>= 1){
            float vs  = __shfl_down_sync(0xffffffffu, bs,  off);
            int   vxy = __shfl_down_sync(0xffffffffu, bxy, off);
            int   vi  = __shfl_down_sync(0xffffffffu, bi,  off);
            if (vs > bs || (vs == bs && vxy < bxy)){ bs = vs; bxy = vxy; bi = vi; }
        }
        if (lane == 0){ w_s[wrp] = bs; w_xy[wrp] = bxy; w_i[wrp] = bi; }
        __syncthreads();
        if (tid == 0){
            float cs = w_s[0]; int cxy = w_xy[0], ci = w_i[0];
#pragma unroll
            for (int t = 1; t < 8; t++){
                if (w_s[t] > cs || (w_s[t] == cs && w_xy[t] < cxy)){
                    cs = w_s[t]; cxy = w_xy[t]; ci = w_i[t];
                }
            }
            sh_best = cs; sh_j = ci; sh_xy = cxy;
        }
        __syncthreads();
        float best = sh_best; int j = sh_j; int jxy = sh_xy;

        if (!(best > -0.5e30f) || j < 0){
            // exhausted: remaining picks have ok=false -> zero rows
            int n0 = (KPICKS - k) * 5;
            float* o0 = out + ((size_t)bb*KPICKS + k)*5;
            for (int t = tid; t < n0; t += NT) o0[t] = 0.f;
            break;
        }

        int jx = jxy & 0xffff, jy = jxy >> 16;
        for (int i = tid; i < count; i += NT){
            int p = xyp[i];
            int dx = (p & 0xffff) - jx; dx = dx < 0 ? -dx : dx;
            int dy = (p >> 16)    - jy; dy = dy < 0 ? -dy : dy;
            if (dx <= 1 && dy <= 1) scp[i] = NEGV;
        }
        if (tid == 0){
            float x1 = 2.f*jx + 1.f,  y1 = 2.f*jy + 1.f;
            float x2 = 2.f*jx + 12.f, y2 = 2.f*jy + 12.f;
            float4 r = g_cand_reg[bb*NPIX + j];
            float q1 = fmaf(r.x, 11.f, x1);
            float q2 = fmaf(r.y, 11.f, y1);
            float q3 = fmaf(r.z, 11.f, x2);
            float q4 = fmaf(r.w, 11.f, y2);
            float rw = q3 - q1, rh = q4 - q2;
            float l = fmaxf(rw, rh);
            float nx1 = q1 + rw*0.5f - l*0.5f;
            float ny1 = q2 + rh*0.5f - l*0.5f;
            float* o = out + ((size_t)bb*KPICKS + k)*5;
            o[0] = nx1; o[1] = ny1; o[2] = nx1 + l; o[3] = ny1 + l; o[4] = best;
        }
        __syncthreads();
    }
}

// ============================================================
extern "C" void kernel_launch(void* const* d_in, const int* in_sizes, int n_in,
                              void* d_out, int out_size)
{
    const float* im   = (const float*)d_in[0];
    const float* c1w  = (const float*)d_in[1];
    const float* c1b  = (const float*)d_in[2];
    const float* p1   = (const float*)d_in[3];
    const float* c2w  = (const float*)d_in[4];
    const float* c2b  = (const float*)d_in[5];
    const float* p2   = (const float*)d_in[6];
    const float* c3w  = (const float*)d_in[7];
    const float* c3b  = (const float*)d_in[8];
    const float* p3   = (const float*)d_in[9];
    const float* c41w = (const float*)d_in[10];
    const float* c41b = (const float*)d_in[11];
    const float* c42w = (const float*)d_in[12];
    const float* c42b = (const float*)d_in[13];
    float* out = (float*)d_out;

    dim3 blk(32, 8, 1);
    dim3 g1((WPP    + 31)/32, (HPP + 7)/8, BB);
    dim3 g2((PAIRS2 + 31)/32, (H2D + 7)/8, BB);
    dim3 g3((PAIRS3 + 31)/32, (H3D + 7)/8, BB);

    k0_zero<<<1, 32>>>();
    k1_conv1_pool<<<g1, blk>>>(im, c1w, c1b, p1);
    k2_conv2<<<g2, blk>>>(c2w, c2b, p2);
    k3_conv3_heads<<<g3, blk>>>(c3w, c3b, p3, c41w, c41b, c42w, c42b);
    k4_nms<<<BB, 256>>>(out);
}

// round 3
// speedup vs baseline: 2.3708x; 1.6775x over previous
#include <cuda_runtime.h>
#include <math.h>

typedef unsigned long long ull;

// ---- problem constants ----
#define BB  16
#define HH  384
#define WW  512
#define HPP 191
#define WPP 255
#define H2D 189
#define W2D 253
#define H3D 187
#define W3D 251
#define NPIX (H3D*W3D)   // 46937
#define NEGV (-1e30f)
#define THRESH_V 0.6f
#define KPICKS 128
#define CAP 5600
#define SP  260          // padded row stride (mult of 4)
#define PH  196          // padded plane height

// ---- scratch (zero-initialized device globals; padding stays 0 -> deterministic) ----
__device__ __align__(16) float  g_pool[BB*10*PH*SP];
__device__ __align__(16) float  g_h2[BB*16*PH*SP];
__device__ int    g_cnt[BB];
__device__ int    g_cand[BB*NPIX];      // packed (y<<16)|x
__device__ float  g_cand_sc[BB*NPIX];
__device__ float4 g_cand_reg[BB*NPIX];

// ---- f32x2 helpers ----
__device__ __forceinline__ ull pack2(float lo, float hi){
    ull r; asm("mov.b64 %0, {%1, %2};" : "=l"(r) : "f"(lo), "f"(hi)); return r;
}
__device__ __forceinline__ void unpack2(ull v, float &lo, float &hi){
    asm("mov.b64 {%0, %1}, %2;" : "=f"(lo), "=f"(hi) : "l"(v));
}
__device__ __forceinline__ void fma2(ull &d, ull a, ull b){
    asm("fma.rn.f32x2 %0, %1, %2, %0;" : "+l"(d) : "l"(a), "l"(b));
}

// ============================================================
__global__ void k0_zero(){
    if (threadIdx.x < BB) g_cnt[threadIdx.x] = 0;
}

// ============================================================
// K1: normalize + conv1(3x3,3->10) + PReLU + maxpool2x2
// weights packed as oc-pairs {w_2q, w_2q+1}; inputs duplicated.
// 1 thread = 1 pooled pixel (4 conv px), acc[4 px][5 ocpairs]
// ============================================================
__global__ __launch_bounds__(256) void k1_conv1_pool(const float* __restrict__ im,
                              const float* __restrict__ w,   // (10,3,3,3)
                              const float* __restrict__ b,
                              const float* __restrict__ p)
{
    __shared__ __align__(16) ull sw[135];   // [(c*9+k)*5 + q]
    __shared__ float sb[10], sp[10];
    int tid = threadIdx.y * 32 + threadIdx.x;
    for (int i = tid; i < 135; i += 256){
        int ck = i / 5, q = i % 5;
        sw[i] = pack2(w[(2*q)*27 + ck], w[(2*q+1)*27 + ck]);
    }
    if (tid < 10){ sb[tid] = b[tid]; sp[tid] = p[tid]; }
    __syncthreads();

    int ox = blockIdx.x * 32 + threadIdx.x;
    int oy = blockIdx.y * 8  + threadIdx.y;
    int bb = blockIdx.z;
    if (ox >= WPP || oy >= HPP) return;

    ull acc[4][5];
#pragma unroll
    for (int q = 0; q < 5; q++){
        ull bi = pack2(sb[2*q], sb[2*q+1]);
        acc[0][q] = bi; acc[1][q] = bi; acc[2][q] = bi; acc[3][q] = bi;
    }

#pragma unroll
    for (int c = 0; c < 3; c++){
        const float* base = im + ((bb*3 + c)*HH + 2*oy)*WW + 2*ox;
        ull du[4][4];
#pragma unroll
        for (int r = 0; r < 4; r++){
            float2 u01 = *reinterpret_cast<const float2*>(base + r*WW);
            float2 u23 = *reinterpret_cast<const float2*>(base + r*WW + 2);
            float v0 = (u01.x - 127.5f)*0.0078125f;
            float v1 = (u01.y - 127.5f)*0.0078125f;
            float v2 = (u23.x - 127.5f)*0.0078125f;
            float v3 = (u23.y - 127.5f)*0.0078125f;
            du[r][0] = pack2(v0,v0); du[r][1] = pack2(v1,v1);
            du[r][2] = pack2(v2,v2); du[r][3] = pack2(v3,v3);
        }
#pragma unroll
        for (int ky = 0; ky < 3; ky++)
#pragma unroll
        for (int kx = 0; kx < 3; kx++){
            const ull* wq = &sw[(c*9 + ky*3 + kx)*5];
#pragma unroll
            for (int q = 0; q < 5; q++){
                ull wv = wq[q];
                fma2(acc[0][q], du[ky  ][kx  ], wv);
                fma2(acc[1][q], du[ky  ][kx+1], wv);
                fma2(acc[2][q], du[ky+1][kx  ], wv);
                fma2(acc[3][q], du[ky+1][kx+1], wv);
            }
        }
    }
#pragma unroll
    for (int q = 0; q < 5; q++){
        float h[4][2];
#pragma unroll
        for (int pp = 0; pp < 4; pp++) unpack2(acc[pp][q], h[pp][0], h[pp][1]);
#pragma unroll
        for (int s = 0; s < 2; s++){
            int oc = 2*q + s;
            float al = sp[oc];
            float m = -INFINITY;
#pragma unroll
            for (int pp = 0; pp < 4; pp++){
                float v = h[pp][s];
                v = v > 0.f ? v : al*v;
                m = fmaxf(m, v);
            }
            g_pool[((bb*10 + oc)*PH + oy)*SP + ox] = m;
        }
    }
}

// ============================================================
// K2: conv2(3x3,10->16) + PReLU
// 1 thread = 2 px (x0, x0+1), full 16 oc as 8 ocpairs
// ============================================================
__global__ __launch_bounds__(256) void k2_conv2(const float* __restrict__ w,  // (16,10,3,3)
                         const float* __restrict__ b,
                         const float* __restrict__ p)
{
    __shared__ __align__(16) ull sw[720];   // [(c*9+k)*8 + q]
    __shared__ float sb[16], sp[16];
    int tid = threadIdx.y * 32 + threadIdx.x;
    for (int i = tid; i < 720; i += 256){
        int ck = i >> 3, q = i & 7;
        sw[i] = pack2(w[(2*q)*90 + ck], w[(2*q+1)*90 + ck]);
    }
    if (tid < 16){ sb[tid] = b[tid]; sp[tid] = p[tid]; }
    __syncthreads();

    int x0 = blockIdx.x * 64 + threadIdx.x * 2;   // <= 254; reads <= 257 < SP
    int oy = blockIdx.y * 8  + threadIdx.y;       // <= 191; reads rows <= 193 < PH
    int bb = blockIdx.z;

    ull acc[2][8];
#pragma unroll
    for (int q = 0; q < 8; q++){
        ull bi = pack2(sb[2*q], sb[2*q+1]);
        acc[0][q] = bi; acc[1][q] = bi;
    }

    for (int c = 0; c < 10; c++){
        const float* base = g_pool + ((bb*10 + c)*PH + oy)*SP + x0;
        ull du[3][4];
#pragma unroll
        for (int r = 0; r < 3; r++){
            float2 a2 = *reinterpret_cast<const float2*>(base + r*SP);
            float2 b2 = *reinterpret_cast<const float2*>(base + r*SP + 2);
            du[r][0] = pack2(a2.x,a2.x); du[r][1] = pack2(a2.y,a2.y);
            du[r][2] = pack2(b2.x,b2.x); du[r][3] = pack2(b2.y,b2.y);
        }
#pragma unroll
        for (int ky = 0; ky < 3; ky++)
#pragma unroll
        for (int kx = 0; kx < 3; kx++){
            const ulonglong2* wp = reinterpret_cast<const ulonglong2*>(&sw[(c*9 + ky*3 + kx)*8]);
            ull u0 = du[ky][kx], u1 = du[ky][kx+1];
#pragma unroll
            for (int g = 0; g < 4; g++){
                ulonglong2 wv = wp[g];
                fma2(acc[0][2*g],   u0, wv.x);
                fma2(acc[0][2*g+1], u0, wv.y);
                fma2(acc[1][2*g],   u1, wv.x);
                fma2(acc[1][2*g+1], u1, wv.y);
            }
        }
    }
#pragma unroll
    for (int q = 0; q < 8; q++){
        float a0,a1,b0,b1;
        unpack2(acc[0][q], a0, a1);   // px0: oc 2q, 2q+1
        unpack2(acc[1][q], b0, b1);   // px1: oc 2q, 2q+1
        float alo = sp[2*q], ahi = sp[2*q+1];
        a0 = a0 > 0.f ? a0 : alo*a0;
        b0 = b0 > 0.f ? b0 : alo*b0;
        a1 = a1 > 0.f ? a1 : ahi*a1;
        b1 = b1 > 0.f ? b1 : ahi*b1;
        *reinterpret_cast<float2*>(&g_h2[((bb*16 + 2*q  )*PH + oy)*SP + x0]) = make_float2(a0, b0);
        *reinterpret_cast<float2*>(&g_h2[((bb*16 + 2*q+1)*PH + oy)*SP + x0]) = make_float2(a1, b1);
    }
}

// ============================================================
// K3: conv3(3x3,16->32)+PReLU + fused 1x1 heads + append
// 1 thread = 2 px, full 32 oc as 16 ocpairs (LDS:FMA2 = 1:8)
// ============================================================
__global__ __launch_bounds__(256) void k3_conv3_heads(const float* __restrict__ w3, // (32,16,3,3)
                               const float* __restrict__ b3,
                               const float* __restrict__ p3,
                               const float* __restrict__ w41, const float* __restrict__ b41,
                               const float* __restrict__ w42, const float* __restrict__ b42)
{
    __shared__ __align__(16) ull sw[2304];  // [(c*9+k)*16 + q]
    __shared__ float sb[32], sp[32];
    __shared__ float sw41[64], sw42[128], sb41[2], sb42[4];
    int tid = threadIdx.y * 32 + threadIdx.x;
    for (int i = tid; i < 2304; i += 256){
        int ck = i >> 4, q = i & 15;
        sw[i] = pack2(w3[(2*q)*144 + ck], w3[(2*q+1)*144 + ck]);
    }
    if (tid < 32){ sb[tid] = b3[tid]; sp[tid] = p3[tid]; }
    if (tid < 64)  sw41[tid] = w41[tid];
    if (tid < 128) sw42[tid] = w42[tid];
    if (tid < 2)   sb41[tid] = b41[tid];
    if (tid < 4)   sb42[tid] = b42[tid];
    __syncthreads();

    int x0 = blockIdx.x * 64 + threadIdx.x * 2;   // <= 254; reads <= 257 < SP
    int oy = blockIdx.y * 8  + threadIdx.y;       // <= 191; reads rows <= 193 < PH
    int bb = blockIdx.z;

    ull acc[2][16];
#pragma unroll
    for (int q = 0; q < 16; q++){
        ull bi = pack2(sb[2*q], sb[2*q+1]);
        acc[0][q] = bi; acc[1][q] = bi;
    }

    for (int c = 0; c < 16; c++){
        const float* base = g_h2 + ((bb*16 + c)*PH + oy)*SP + x0;
        ull du[3][4];
#pragma unroll
        for (int r = 0; r < 3; r++){
            float2 a2 = *reinterpret_cast<const float2*>(base + r*SP);
            float2 b2 = *reinterpret_cast<const float2*>(base + r*SP + 2);
            du[r][0] = pack2(a2.x,a2.x); du[r][1] = pack2(a2.y,a2.y);
            du[r][2] = pack2(b2.x,b2.x); du[r][3] = pack2(b2.y,b2.y);
        }
#pragma unroll
        for (int ky = 0; ky < 3; ky++)
#pragma unroll
        for (int kx = 0; kx < 3; kx++){
            const ulonglong2* wp = reinterpret_cast<const ulonglong2*>(&sw[(c*9 + ky*3 + kx)*16]);
            ull u0 = du[ky][kx], u1 = du[ky][kx+1];
#pragma unroll
            for (int g = 0; g < 8; g++){
                ulonglong2 wv = wp[g];
                fma2(acc[0][2*g],   u0, wv.x);
                fma2(acc[0][2*g+1], u0, wv.y);
                fma2(acc[1][2*g],   u1, wv.x);
                fma2(acc[1][2*g+1], u1, wv.y);
            }
        }
    }

    // heads: per-pixel full 32-channel dot products
    float l0[2], l1[2], r0[2], r1[2], r2[2], r3[2];
#pragma unroll
    for (int pp = 0; pp < 2; pp++){
        l0[pp] = sb41[0]; l1[pp] = sb41[1];
        r0[pp] = sb42[0]; r1[pp] = sb42[1]; r2[pp] = sb42[2]; r3[pp] = sb42[3];
    }
#pragma unroll
    for (int q = 0; q < 16; q++){
        float wA0 = sw41[2*q], wA1 = sw41[2*q+1];
        float wB0 = sw41[32+2*q], wB1 = sw41[32+2*q+1];
        float q00 = sw42[2*q],    q01 = sw42[2*q+1];
        float q10 = sw42[32+2*q], q11 = sw42[32+2*q+1];
        float q20 = sw42[64+2*q], q21 = sw42[64+2*q+1];
        float q30 = sw42[96+2*q], q31 = sw42[96+2*q+1];
        float alo = sp[2*q], ahi = sp[2*q+1];
#pragma unroll
        for (int pp = 0; pp < 2; pp++){
            float hA, hB; unpack2(acc[pp][q], hA, hB);
            hA = hA > 0.f ? hA : alo*hA;
            hB = hB > 0.f ? hB : ahi*hB;
            l0[pp] = fmaf(hA, wA0, fmaf(hB, wA1, l0[pp]));
            l1[pp] = fmaf(hA, wB0, fmaf(hB, wB1, l1[pp]));
            r0[pp] = fmaf(hA, q00, fmaf(hB, q01, r0[pp]));
            r1[pp] = fmaf(hA, q10, fmaf(hB, q11, r1[pp]));
            r2[pp] = fmaf(hA, q20, fmaf(hB, q21, r2[pp]));
            r3[pp] = fmaf(hA, q30, fmaf(hB, q31, r3[pp]));
        }
    }
    if (oy < H3D){
#pragma unroll
        for (int pp = 0; pp < 2; pp++){
            int x = x0 + pp;
            if (x >= W3D) continue;
            float prob = 1.f / (1.f + expf(l0[pp] - l1[pp]));
            if (prob >= THRESH_V){
                int pos = atomicAdd(&g_cnt[bb], 1);
                if (pos < NPIX){
                    g_cand[bb*NPIX + pos]    = (oy << 16) | x;
                    g_cand_sc[bb*NPIX + pos] = prob;
                    g_cand_reg[bb*NPIX + pos] = make_float4(r0[pp], r1[pp], r2[pp], r3[pp]);
                }
            }
        }
    }
}

// ============================================================
// K4: per-batch iterative argmax NMS on unordered candidate list.
// Tie-break (score desc, packed xy asc) == pixel-index order.
// IoU>0.5 for 12x12 stride-2 boxes  <=>  |dx|<=1 && |dy|<=1.
// ============================================================
__global__ void k4_nms(float* __restrict__ out)
{
    const int NT = 256;
    int bb = blockIdx.x, tid = threadIdx.x;
    int lane = tid & 31, wrp = tid >> 5;

    __shared__ float s_sc[CAP];
    __shared__ int   s_xy[CAP];
    __shared__ float w_s[8];
    __shared__ int   w_xy[8], w_i[8];
    __shared__ float sh_best;
    __shared__ int   sh_j, sh_xy;

    int count = g_cnt[bb];
    if (count > NPIX) count = NPIX;
    bool insh = (count <= CAP);
    float* scp;
    const int* xyp;
    if (insh){
        for (int i = tid; i < count; i += NT){
            s_sc[i] = g_cand_sc[bb*NPIX + i];
            s_xy[i] = g_cand[bb*NPIX + i];
        }
        scp = s_sc; xyp = s_xy;
    } else {
        scp = g_cand_sc + bb*NPIX;
        xyp = g_cand + bb*NPIX;
    }
    __syncthreads();

    for (int k = 0; k < KPICKS; k++){
        float bs = -INFINITY; int bxy = 0x7fffffff; int bi = -1;
        for (int i = tid; i < count; i += NT){
            float v = scp[i]; int xy = xyp[i];
            if (v > bs || (v == bs && xy < bxy)){ bs = v; bxy = xy; bi = i; }
        }
#pragma unroll
        for (int off = 16; off > 0; off >>= 1){
            float vs  = __shfl_down_sync(0xffffffffu, bs,  off);
            int   vxy = __shfl_down_sync(0xffffffffu, bxy, off);
            int   vi  = __shfl_down_sync(0xffffffffu, bi,  off);
            if (vs > bs || (vs == bs && vxy < bxy)){ bs = vs; bxy = vxy; bi = vi; }
        }
        if (lane == 0){ w_s[wrp] = bs; w_xy[wrp] = bxy; w_i[wrp] = bi; }
        __syncthreads();
        if (tid == 0){
            float cs = w_s[0]; int cxy = w_xy[0], ci = w_i[0];
#pragma unroll
            for (int t = 1; t < 8; t++){
                if (w_s[t] > cs || (w_s[t] == cs && w_xy[t] < cxy)){
                    cs = w_s[t]; cxy = w_xy[t]; ci = w_i[t];
                }
            }
            sh_best = cs; sh_j = ci; sh_xy = cxy;
        }
        __syncthreads();
        float best = sh_best; int j = sh_j; int jxy = sh_xy;

        if (!(best > -0.5e30f) || j < 0){
            int n0 = (KPICKS - k) * 5;
            float* o0 = out + ((size_t)bb*KPICKS + k)*5;
            for (int t = tid; t < n0; t += NT) o0[t] = 0.f;
            break;
        }

        int jx = jxy & 0xffff, jy = jxy >> 16;
        for (int i = tid; i < count; i += NT){
            int p = xyp[i];
            int dx = (p & 0xffff) - jx; dx = dx < 0 ? -dx : dx;
            int dy = (p >> 16)    - jy; dy = dy < 0 ? -dy : dy;
            if (dx <= 1 && dy <= 1) scp[i] = NEGV;
        }
        if (tid == 0){
            float x1 = 2.f*jx + 1.f,  y1 = 2.f*jy + 1.f;
            float x2 = 2.f*jx + 12.f, y2 = 2.f*jy + 12.f;
            float4 r = g_cand_reg[bb*NPIX + j];
            float q1 = fmaf(r.x, 11.f, x1);
            float q2 = fmaf(r.y, 11.f, y1);
            float q3 = fmaf(r.z, 11.f, x2);
            float q4 = fmaf(r.w, 11.f, y2);
            float rw = q3 - q1, rh = q4 - q2;
            float l = fmaxf(rw, rh);
            float nx1 = q1 + rw*0.5f - l*0.5f;
            float ny1 = q2 + rh*0.5f - l*0.5f;
            float* o = out + ((size_t)bb*KPICKS + k)*5;
            o[0] = nx1; o[1] = ny1; o[2] = nx1 + l; o[3] = ny1 + l; o[4] = best;
        }
        __syncthreads();
    }
}

// ============================================================
extern "C" void kernel_launch(void* const* d_in, const int* in_sizes, int n_in,
                              void* d_out, int out_size)
{
    const float* im   = (const float*)d_in[0];
    const float* c1w  = (const float*)d_in[1];
    const float* c1b  = (const float*)d_in[2];
    const float* p1   = (const float*)d_in[3];
    const float* c2w  = (const float*)d_in[4];
    const float* c2b  = (const float*)d_in[5];
    const float* p2   = (const float*)d_in[6];
    const float* c3w  = (const float*)d_in[7];
    const float* c3b  = (const float*)d_in[8];
    const float* p3   = (const float*)d_in[9];
    const float* c41w = (const float*)d_in[10];
    const float* c41b = (const float*)d_in[11];
    const float* c42w = (const float*)d_in[12];
    const float* c42b = (const float*)d_in[13];
    float* out = (float*)d_out;

    dim3 blk(32, 8, 1);
    dim3 g1(8, 24, BB);   // 32 px * 8 rows per block, 255x191
    dim3 g2(4, 24, BB);   // 64 px * 8 rows per block, 253x189(+pad rows)
    dim3 g3(4, 24, BB);   // 64 px * 8 rows per block, 251x187(+pad rows)

    k0_zero<<<1, 32>>>();
    k1_conv1_pool<<<g1, blk>>>(im, c1w, c1b, p1);
    k2_conv2<<<g2, blk>>>(c2w, c2b, p2);
    k3_conv3_heads<<<g3, blk>>>(c3w, c3b, p3, c41w, c41b, c42w, c42b);
    k4_nms<<<BB, 256>>>(out);
}